// round 1
// baseline (speedup 1.0000x reference)
#include <cuda_runtime.h>
#include <math.h>

// ---------------- problem constants ----------------
#define Bb 4
#define Cc 256
#define Hh 80
#define Ww 80
#define Nq 300
#define IDim 128
#define HID 512
#define H2 160
#define W2 160
#define HW (Hh*Ww)
#define CHW (Cc*HW)

// ---------------- device scratch ----------------
__device__ float g_x[Bb*CHW];      // block0 output
__device__ float g_y[Bb*CHW];      // block1 output (final spatial)
__device__ float g_t[Bb*CHW];      // dw+LN temp
__device__ float g_q1[Bb*Nq*HID];
__device__ float g_q2[Bb*Nq*HID];
__device__ float g_q4[Bb*Nq*IDim];
__device__ float g_qq[Bb*Nq*Cc];
__device__ float g_off[Bb*Nq];
__device__ float g_m[Bb*Nq*HW];    // mask at 80x80

// ---------------- depthwise 3x3 conv (SAME), + bias ----------------
__global__ void dw_kernel(const float* __restrict__ x, const float* __restrict__ w,
                          const float* __restrict__ b, float* __restrict__ out)
{
    int idx = blockIdx.x * blockDim.x + threadIdx.x;
    if (idx >= Bb*CHW) return;
    int wq = idx % Ww;
    int hq = (idx / Ww) % Hh;
    int c  = (idx / HW) % Cc;
    int bb = idx / CHW;
    const float* xp = x + (long)bb*CHW + (long)c*HW;
    const float* wp = w + c*9;
    float acc = b[c];
#pragma unroll
    for (int kh = 0; kh < 3; kh++) {
        int h = hq + kh - 1;
        if (h < 0 || h >= Hh) continue;
#pragma unroll
        for (int kw = 0; kw < 3; kw++) {
            int ww2 = wq + kw - 1;
            if (ww2 < 0 || ww2 >= Ww) continue;
            acc += wp[kh*3+kw] * xp[h*Ww + ww2];
        }
    }
    out[idx] = acc;
}

// ---------------- LayerNorm over channel dim (per pixel), in place ----------------
__global__ void ln_kernel(float* __restrict__ t, const float* __restrict__ lw,
                          const float* __restrict__ lb)
{
    int p = blockIdx.x * blockDim.x + threadIdx.x;
    if (p >= Bb*HW) return;
    int bb = p / HW;
    int pix = p % HW;
    float* base = t + (long)bb*CHW + pix;
    float s = 0.f, s2 = 0.f;
#pragma unroll 4
    for (int c = 0; c < Cc; c++) {
        float v = base[(long)c*HW];
        s += v; s2 += v*v;
    }
    float mean = s * (1.0f/Cc);
    float var  = s2 * (1.0f/Cc) - mean*mean;
    float inv  = rsqrtf(var + 1e-6f);
#pragma unroll 4
    for (int c = 0; c < Cc; c++) {
        float v = base[(long)c*HW];
        base[(long)c*HW] = (v - mean) * inv * lw[c] + lb[c];
    }
}

// ---------------- generic tiled fp32 GEMM ----------------
// C[m,n] = act( sum_k A[m,k] * (TRANSB ? B[n,k] : B[k,n]) + bias ) (+ resid)
// ACT: 0=none, 1=relu, 2=gelu(exact)
// BM=BN=128, BK=16, 256 threads, 8x8 per thread.
#define BM 128
#define BN 128
#define BK 16

template<int ACT, bool TRANSB, bool BIAS_ROW>
__global__ void gemm_kernel(const float* __restrict__ A, const float* __restrict__ Bm,
                            const float* __restrict__ bias, const float* __restrict__ resid,
                            float* __restrict__ C,
                            int M, int N, int K,
                            long sA, long sB, long sC)
{
    int bz = blockIdx.z;
    A  += bz * sA;
    Bm += bz * sB;
    C  += bz * sC;
    const float* R = resid ? resid + bz * sC : nullptr;

    int m0 = blockIdx.y * BM;
    int n0 = blockIdx.x * BN;

    __shared__ float As[BK][BM];
    __shared__ float Bs[BK][BN];

    int tid = threadIdx.x;
    int tx = tid & 15;        // 0..15 -> n groups of 8
    int ty = tid >> 4;        // 0..15 -> m groups of 8

    float acc[8][8];
#pragma unroll
    for (int i = 0; i < 8; i++)
#pragma unroll
        for (int j = 0; j < 8; j++) acc[i][j] = 0.f;

    for (int k0 = 0; k0 < K; k0 += BK) {
        // load A tile: BM x BK
#pragma unroll
        for (int r = 0; r < 8; r++) {
            int m = (tid >> 4) + r * 16;     // 0..127
            int k = tid & 15;
            int gm = m0 + m;
            float v = 0.f;
            if (gm < M) v = A[(long)gm * K + k0 + k];
            As[k][m] = v;
        }
        // load B tile: BK x BN
        if (TRANSB) {
#pragma unroll
            for (int r = 0; r < 8; r++) {
                int n = (tid >> 4) + r * 16;
                int k = tid & 15;
                int gn = n0 + n;
                float v = 0.f;
                if (gn < N) v = Bm[(long)gn * K + k0 + k];
                Bs[k][n] = v;
            }
        } else {
#pragma unroll
            for (int r = 0; r < 8; r++) {
                int n = tid & 127;
                int k = (tid >> 7) + r * 2;
                int gn = n0 + n;
                float v = 0.f;
                if (gn < N) v = Bm[(long)(k0 + k) * N + gn];
                Bs[k][n] = v;
            }
        }
        __syncthreads();

#pragma unroll
        for (int k = 0; k < BK; k++) {
            float a[8], bfr[8];
#pragma unroll
            for (int i = 0; i < 8; i++) a[i] = As[k][ty*8 + i];
#pragma unroll
            for (int j = 0; j < 8; j++) bfr[j] = Bs[k][tx*8 + j];
#pragma unroll
            for (int i = 0; i < 8; i++)
#pragma unroll
                for (int j = 0; j < 8; j++)
                    acc[i][j] = fmaf(a[i], bfr[j], acc[i][j]);
        }
        __syncthreads();
    }

#pragma unroll
    for (int i = 0; i < 8; i++) {
        int gm = m0 + ty*8 + i;
        if (gm >= M) continue;
#pragma unroll
        for (int j = 0; j < 8; j++) {
            int gn = n0 + tx*8 + j;
            if (gn >= N) continue;
            float v = acc[i][j];
            if (bias) v += BIAS_ROW ? bias[gm] : bias[gn];
            if (ACT == 1) v = fmaxf(v, 0.f);
            if (ACT == 2) v = 0.5f * v * (1.f + erff(v * 0.70710678118654752f));
            if (R) v += R[(long)gm * N + gn];
            C[(long)gm * N + gn] = v;
        }
    }
}

// ---------------- per-query offset: q4 . sproj_b + head_bias ----------------
__global__ void off_kernel(const float* __restrict__ q4, const float* __restrict__ sb,
                           const float* __restrict__ hb, float* __restrict__ off)
{
    int n = blockIdx.x * blockDim.x + threadIdx.x;
    if (n >= Bb*Nq) return;
    float s = hb[0];
#pragma unroll 4
    for (int i = 0; i < IDim; i++) s += q4[(long)n*IDim + i] * sb[i];
    off[n] = s;
}

// ---------------- bilinear 2x upsample (align_corners=False) + offset ----------------
__global__ void upsample_kernel(const float* __restrict__ m, const float* __restrict__ off,
                                float* __restrict__ out)
{
    long idx = (long)blockIdx.x * blockDim.x + threadIdx.x;
    const long total = (long)Bb*Nq*H2*W2;
    if (idx >= total) return;
    int w2 = (int)(idx % W2);
    int h2 = (int)((idx / W2) % H2);
    long bn = idx / ((long)W2*H2);

    float fh = h2 * 0.5f - 0.25f;
    int h0f = (int)floorf(fh);
    float wh1 = fh - (float)h0f;
    int h0 = max(h0f, 0), h1 = min(h0f + 1, Hh - 1);

    float fw = w2 * 0.5f - 0.25f;
    int w0f = (int)floorf(fw);
    float ww1 = fw - (float)w0f;
    int w0 = max(w0f, 0), w1 = min(w0f + 1, Ww - 1);

    const float* mp = m + bn * (long)HW;
    float v00 = mp[h0*Ww + w0], v01 = mp[h0*Ww + w1];
    float v10 = mp[h1*Ww + w0], v11 = mp[h1*Ww + w1];
    float v = (1.f - wh1) * ((1.f - ww1)*v00 + ww1*v01)
            +        wh1  * ((1.f - ww1)*v10 + ww1*v11);
    out[idx] = v + off[bn];
}

// ---------------- launcher ----------------
extern "C" void kernel_launch(void* const* d_in, const int* in_sizes, int n_in,
                              void* d_out, int out_size)
{
    const float* spat   = (const float*)d_in[0];
    const float* qf     = (const float*)d_in[1];
    const float* dw_w   = (const float*)d_in[2];
    const float* dw_b   = (const float*)d_in[3];
    const float* ln_w   = (const float*)d_in[4];
    const float* ln_b   = (const float*)d_in[5];
    const float* pw_w   = (const float*)d_in[6];
    const float* pw_b   = (const float*)d_in[7];
    const float* sproj_w= (const float*)d_in[8];
    const float* sproj_b= (const float*)d_in[9];
    const float* mlp_w1 = (const float*)d_in[10];
    const float* mlp_b1 = (const float*)d_in[11];
    const float* mlp_w2 = (const float*)d_in[12];
    const float* mlp_b2 = (const float*)d_in[13];
    const float* mlp_w3 = (const float*)d_in[14];
    const float* mlp_b3 = (const float*)d_in[15];
    const float* qproj_w= (const float*)d_in[16];
    const float* qproj_b= (const float*)d_in[17];
    const float* head_b = (const float*)d_in[18];
    float* out = (float*)d_out;

    float *px, *py, *pt, *pq1, *pq2, *pq4, *pqq, *poff, *pm;
    cudaGetSymbolAddress((void**)&px,  g_x);
    cudaGetSymbolAddress((void**)&py,  g_y);
    cudaGetSymbolAddress((void**)&pt,  g_t);
    cudaGetSymbolAddress((void**)&pq1, g_q1);
    cudaGetSymbolAddress((void**)&pq2, g_q2);
    cudaGetSymbolAddress((void**)&pq4, g_q4);
    cudaGetSymbolAddress((void**)&pqq, g_qq);
    cudaGetSymbolAddress((void**)&poff,g_off);
    cudaGetSymbolAddress((void**)&pm,  g_m);

    const int elems = Bb*CHW;
    const int pix   = Bb*HW;

    // ---- spatial block 0: dw -> LN -> pw GEMM + GELU + residual ----
    dw_kernel<<<(elems+255)/256, 256>>>(spat, dw_w, dw_b, pt);
    ln_kernel<<<(pix+255)/256, 256>>>(pt, ln_w, ln_b);
    gemm_kernel<2,false,true><<<dim3((HW+BN-1)/BN, (Cc+BM-1)/BM, Bb), 256>>>(
        pw_w, pt, pw_b, spat, px, Cc, HW, Cc, 0, CHW, CHW);

    // ---- spatial block 1 ----
    dw_kernel<<<(elems+255)/256, 256>>>(px, dw_w + Cc*9, dw_b + Cc, pt);
    ln_kernel<<<(pix+255)/256, 256>>>(pt, ln_w + Cc, ln_b + Cc);
    gemm_kernel<2,false,true><<<dim3((HW+BN-1)/BN, (Cc+BM-1)/BM, Bb), 256>>>(
        pw_w + Cc*Cc, pt, pw_b + Cc, px, py, Cc, HW, Cc, 0, CHW, CHW);

    // ---- query MLP chain (M = B*N = 1200 rows) ----
    const int Mq = Bb*Nq;
    gemm_kernel<1,true,false><<<dim3((HID+BN-1)/BN, (Mq+BM-1)/BM, 1), 256>>>(
        qf, mlp_w1, mlp_b1, nullptr, pq1, Mq, HID, Cc, 0, 0, 0);
    gemm_kernel<1,true,false><<<dim3((HID+BN-1)/BN, (Mq+BM-1)/BM, 1), 256>>>(
        pq1, mlp_w2, mlp_b2, nullptr, pq2, Mq, HID, HID, 0, 0, 0);
    gemm_kernel<0,true,false><<<dim3((Cc+BN-1)/BN, (Mq+BM-1)/BM, 1), 256>>>(
        pq2, mlp_w3, mlp_b3, nullptr, pq1, Mq, Cc, HID, 0, 0, 0);   // q3 (reuse q1)
    gemm_kernel<0,true,false><<<dim3((IDim+BN-1)/BN, (Mq+BM-1)/BM, 1), 256>>>(
        pq1, qproj_w, qproj_b, nullptr, pq4, Mq, IDim, Cc, 0, 0, 0); // q4
    // fold sproj into query: qq[n,c] = sum_id q4[n,id] * sproj_w[id,c]
    gemm_kernel<0,false,false><<<dim3((Cc+BN-1)/BN, (Mq+BM-1)/BM, 1), 256>>>(
        pq4, sproj_w, nullptr, nullptr, pqq, Mq, Cc, IDim, 0, 0, 0);
    off_kernel<<<(Mq+255)/256, 256>>>(pq4, sproj_b, head_b, poff);

    // ---- mask GEMM at 80x80: m[b,n,p] = sum_c qq[b,n,c] * y[b,c,p] ----
    gemm_kernel<0,false,false><<<dim3((HW+BN-1)/BN, (Nq+BM-1)/BM, Bb), 256>>>(
        pqq, py, nullptr, nullptr, pm,
        Nq, HW, Cc, (long)Nq*Cc, (long)CHW, (long)Nq*HW);

    // ---- bilinear 2x upsample + per-(b,n) offset ----
    const long total = (long)Bb*Nq*H2*W2;
    upsample_kernel<<<(unsigned)((total+255)/256), 256>>>(pm, poff, out);
}

// round 2
// speedup vs baseline: 1.6159x; 1.6159x over previous
#include <cuda_runtime.h>
#include <math.h>

// ---------------- problem constants ----------------
#define Bb 4
#define Cc 256
#define Hh 80
#define Ww 80
#define Nq 300
#define IDim 128
#define HID 512
#define H2 160
#define W2 160
#define HW (Hh*Ww)
#define CHW (Cc*HW)

// ---------------- device scratch ----------------
__device__ float g_x[Bb*CHW];      // block0 output
__device__ float g_y[Bb*CHW];      // block1 output (final spatial)
__device__ float g_t[Bb*CHW];      // dw temp (pre-LN)
__device__ float g_mean[Bb*HW];
__device__ float g_inv[Bb*HW];
__device__ float g_q1[Bb*Nq*HID];
__device__ float g_q2[Bb*Nq*HID];
__device__ float g_q4[Bb*Nq*IDim];
__device__ float g_qq[Bb*Nq*Cc];
__device__ float g_off[Bb*Nq];
__device__ float g_m[Bb*Nq*HW];    // mask at 80x80

// ---------------- packed f32x2 helpers ----------------
__device__ __forceinline__ void ffma2(unsigned long long& d, unsigned long long a, unsigned long long b) {
    asm("fma.rn.f32x2 %0, %1, %2, %0;" : "+l"(d) : "l"(a), "l"(b));
}
__device__ __forceinline__ unsigned long long bcast2(float a) {
    unsigned int u = __float_as_uint(a);
    unsigned long long r;
    asm("mov.b64 %0, {%1, %1};" : "=l"(r) : "r"(u));
    return r;
}
__device__ __forceinline__ float2 unpack2(unsigned long long v) {
    unsigned int lo, hi;
    asm("mov.b64 {%0, %1}, %2;" : "=r"(lo), "=r"(hi) : "l"(v));
    float2 f; f.x = __uint_as_float(lo); f.y = __uint_as_float(hi);
    return f;
}
__device__ __forceinline__ float gelu_f(float x) {
    return 0.5f * x * (1.0f + erff(x * 0.70710678118654752f));
}

// ---------------- depthwise 3x3 conv (SAME) + bias ----------------
// grid (1, H/4, B*C), block (80, 4). No div/mod in the hot path.
__global__ void dw_kernel(const float* __restrict__ x, const float* __restrict__ w,
                          const float* __restrict__ bia, float* __restrict__ out)
{
    int wq = threadIdx.x;                           // 0..79
    int hq = blockIdx.y * 4 + threadIdx.y;          // 0..79
    int plane = blockIdx.z;                         // b*C + c
    int c = plane & (Cc - 1);
    const float* xp = x + (long)plane * HW;
    const float* wp = w + c * 9;
    float w00 = wp[0], w01 = wp[1], w02 = wp[2];
    float w10 = wp[3], w11 = wp[4], w12 = wp[5];
    float w20 = wp[6], w21 = wp[7], w22 = wp[8];
    float acc = bia[c];

    const float* r0 = xp + (hq - 1) * Ww;
    const float* r1 = xp + hq * Ww;
    const float* r2 = xp + (hq + 1) * Ww;
    bool ht = hq > 0, hb = hq < Hh - 1;
    bool wl = wq > 0, wr = wq < Ww - 1;

    if (ht) {
        if (wl) acc += w00 * r0[wq - 1];
        acc += w01 * r0[wq];
        if (wr) acc += w02 * r0[wq + 1];
    }
    {
        if (wl) acc += w10 * r1[wq - 1];
        acc += w11 * r1[wq];
        if (wr) acc += w12 * r1[wq + 1];
    }
    if (hb) {
        if (wl) acc += w20 * r2[wq - 1];
        acc += w21 * r2[wq];
        if (wr) acc += w22 * r2[wq + 1];
    }
    out[(long)plane * HW + hq * Ww + wq] = acc;
}

// ---------------- LN stats per pixel (mean, inv-std) ----------------
__global__ void stats_kernel(const float* __restrict__ t,
                             float* __restrict__ mean, float* __restrict__ inv)
{
    int p = blockIdx.x * blockDim.x + threadIdx.x;
    if (p >= Bb*HW) return;
    int bb = p / HW;
    int pix = p - bb * HW;
    const float* base = t + (long)bb * CHW + pix;
    float s = 0.f, s2 = 0.f;
#pragma unroll 8
    for (int c = 0; c < Cc; c++) {
        float v = base[(long)c * HW];
        s += v; s2 += v * v;
    }
    float m = s * (1.0f / Cc);
    float var = s2 * (1.0f / Cc) - m * m;
    mean[p] = m;
    inv[p] = rsqrtf(var + 1e-6f);
}

// ---------------- f32x2-packed tiled GEMM ----------------
// C[m,n] = act( sum_k A[m,k] * Bop[k,n] + bias ) (+ resid)
// BMODE 0: Bop = B[k,n] (ld = N), optionally LN-fused per element.
// BMODE 1: Bop = B[n,k] (ld = K).
// BIASM: 0 none, 1 per-m, 2 per-n. ACT: 0 none, 1 relu, 2 gelu.
// Tiles 128x128xBK8, 256 threads, 8x8 per thread via FFMA2 pairs.
#define BK8 8

template<int ACT, int BMODE, int BIASM, bool LNF, bool RES>
__global__ void __launch_bounds__(256, 2)
gemm2(const float* __restrict__ A, const float* __restrict__ B,
      const float* __restrict__ bias, const float* __restrict__ resid,
      const float* __restrict__ lnMean, const float* __restrict__ lnInv,
      const float* __restrict__ lnW, const float* __restrict__ lnB,
      float* __restrict__ C, int M, int N, int K,
      long sA, long sB, long sC)
{
    int z = blockIdx.z;
    A += z * sA; B += z * sB; C += z * sC;
    const float* R = RES ? (resid + z * sC) : nullptr;

    int m0 = blockIdx.y * 128;
    int n0 = blockIdx.x * 128;

    __shared__ float As[2][BK8][128];
    __shared__ float Bs[2][BK8][128];

    int tid = threadIdx.x;
    int tx = tid & 15;
    int ty = tid >> 4;

    // A load indices (row-major M x K)
    int ar = tid >> 1;
    int ak = (tid & 1) * 4;
    // B load indices
    int br = tid >> 1;            // BMODE 1
    int bk1 = (tid & 1) * 4;      // BMODE 1
    int bk0 = tid >> 5;           // BMODE 0 (0..7)
    int bn0 = (tid & 31) * 4;     // BMODE 0

    float4 mvec, ivec;
    if (LNF) {
        mvec = *(const float4*)(lnMean + (long)z * N + n0 + bn0);
        ivec = *(const float4*)(lnInv  + (long)z * N + n0 + bn0);
    }

    unsigned long long acc[8][4];
#pragma unroll
    for (int i = 0; i < 8; i++)
#pragma unroll
        for (int p = 0; p < 4; p++) acc[i][p] = 0ULL;

    const int KT = K >> 3;

    // ---- prefetch tile 0 ----
    float4 aR, bR;
    {
        int gm = m0 + ar;
        aR = make_float4(0.f, 0.f, 0.f, 0.f);
        if (gm < M) aR = *(const float4*)(A + (long)gm * K + ak);
        if (BMODE == 1) {
            bR = *(const float4*)(B + (long)(n0 + br) * K + bk1);
        } else {
            bR = *(const float4*)(B + (long)bk0 * N + n0 + bn0);
            if (LNF) {
                float lwk = lnW[bk0], lbk = lnB[bk0];
                bR.x = (bR.x - mvec.x) * ivec.x * lwk + lbk;
                bR.y = (bR.y - mvec.y) * ivec.y * lwk + lbk;
                bR.z = (bR.z - mvec.z) * ivec.z * lwk + lbk;
                bR.w = (bR.w - mvec.w) * ivec.w * lwk + lbk;
            }
        }
    }
    // store tile 0
    {
        As[0][ak + 0][ar] = aR.x; As[0][ak + 1][ar] = aR.y;
        As[0][ak + 2][ar] = aR.z; As[0][ak + 3][ar] = aR.w;
        if (BMODE == 1) {
            Bs[0][bk1 + 0][br] = bR.x; Bs[0][bk1 + 1][br] = bR.y;
            Bs[0][bk1 + 2][br] = bR.z; Bs[0][bk1 + 3][br] = bR.w;
        } else {
            *(float4*)&Bs[0][bk0][bn0] = bR;
        }
    }
    __syncthreads();

    for (int kt = 0; kt < KT; kt++) {
        int buf = kt & 1;
        int k0n = (kt + 1) << 3;
        if (kt + 1 < KT) {
            int gm = m0 + ar;
            aR = make_float4(0.f, 0.f, 0.f, 0.f);
            if (gm < M) aR = *(const float4*)(A + (long)gm * K + k0n + ak);
            if (BMODE == 1) {
                bR = *(const float4*)(B + (long)(n0 + br) * K + k0n + bk1);
            } else {
                bR = *(const float4*)(B + (long)(k0n + bk0) * N + n0 + bn0);
                if (LNF) {
                    float lwk = lnW[k0n + bk0], lbk = lnB[k0n + bk0];
                    bR.x = (bR.x - mvec.x) * ivec.x * lwk + lbk;
                    bR.y = (bR.y - mvec.y) * ivec.y * lwk + lbk;
                    bR.z = (bR.z - mvec.z) * ivec.z * lwk + lbk;
                    bR.w = (bR.w - mvec.w) * ivec.w * lwk + lbk;
                }
            }
        }

        // ---- compute on buf ----
#pragma unroll
        for (int k = 0; k < BK8; k++) {
            float4 a0 = *(const float4*)&As[buf][k][ty * 4];
            float4 a1 = *(const float4*)&As[buf][k][64 + ty * 4];
            unsigned long long b0 = *(const unsigned long long*)&Bs[buf][k][tx * 4];
            unsigned long long b1 = *(const unsigned long long*)&Bs[buf][k][tx * 4 + 2];
            unsigned long long b2 = *(const unsigned long long*)&Bs[buf][k][64 + tx * 4];
            unsigned long long b3 = *(const unsigned long long*)&Bs[buf][k][64 + tx * 4 + 2];
            float av[8] = {a0.x, a0.y, a0.z, a0.w, a1.x, a1.y, a1.z, a1.w};
#pragma unroll
            for (int i = 0; i < 8; i++) {
                unsigned long long ap = bcast2(av[i]);
                ffma2(acc[i][0], ap, b0);
                ffma2(acc[i][1], ap, b1);
                ffma2(acc[i][2], ap, b2);
                ffma2(acc[i][3], ap, b3);
            }
        }

        if (kt + 1 < KT) {
            int nb = buf ^ 1;
            As[nb][ak + 0][ar] = aR.x; As[nb][ak + 1][ar] = aR.y;
            As[nb][ak + 2][ar] = aR.z; As[nb][ak + 3][ar] = aR.w;
            if (BMODE == 1) {
                Bs[nb][bk1 + 0][br] = bR.x; Bs[nb][bk1 + 1][br] = bR.y;
                Bs[nb][bk1 + 2][br] = bR.z; Bs[nb][bk1 + 3][br] = bR.w;
            } else {
                *(float4*)&Bs[nb][bk0][bn0] = bR;
            }
            __syncthreads();
        }
    }

    // ---- epilogue ----
#pragma unroll
    for (int i = 0; i < 8; i++) {
        int gm = m0 + ((i < 4) ? (ty * 4 + i) : (64 + ty * 4 + (i - 4)));
        if (gm >= M) continue;
        float bm = 0.f;
        if (BIASM == 1) bm = bias[gm];
#pragma unroll
        for (int g = 0; g < 2; g++) {
            int n = n0 + g * 64 + tx * 4;
            float2 c0 = unpack2(acc[i][2 * g]);
            float2 c1 = unpack2(acc[i][2 * g + 1]);
            float4 v = make_float4(c0.x, c0.y, c1.x, c1.y);
            if (BIASM == 1) { v.x += bm; v.y += bm; v.z += bm; v.w += bm; }
            if (BIASM == 2) {
                float4 b4 = *(const float4*)&bias[n];
                v.x += b4.x; v.y += b4.y; v.z += b4.z; v.w += b4.w;
            }
            if (ACT == 1) {
                v.x = fmaxf(v.x, 0.f); v.y = fmaxf(v.y, 0.f);
                v.z = fmaxf(v.z, 0.f); v.w = fmaxf(v.w, 0.f);
            }
            if (ACT == 2) {
                v.x = gelu_f(v.x); v.y = gelu_f(v.y);
                v.z = gelu_f(v.z); v.w = gelu_f(v.w);
            }
            if (RES) {
                float4 r4 = *(const float4*)&R[(long)gm * N + n];
                v.x += r4.x; v.y += r4.y; v.z += r4.z; v.w += r4.w;
            }
            *(float4*)&C[(long)gm * N + n] = v;
        }
    }
}

// ---------------- per-query offset: q4 . sproj_b + head_bias ----------------
__global__ void off_kernel(const float* __restrict__ q4, const float* __restrict__ sb,
                           const float* __restrict__ hb, float* __restrict__ off)
{
    int n = blockIdx.x * blockDim.x + threadIdx.x;
    if (n >= Bb*Nq) return;
    float s = hb[0];
#pragma unroll 8
    for (int i = 0; i < IDim; i++) s += q4[(long)n * IDim + i] * sb[i];
    off[n] = s;
}

// ---------------- bilinear 2x upsample + offset, float4 stores ----------------
__global__ void upsample_kernel(const float* __restrict__ m, const float* __restrict__ off,
                                float* __restrict__ out)
{
    long idx = (long)blockIdx.x * blockDim.x + threadIdx.x;
    const long tot4 = (long)Bb * Nq * H2 * (W2 / 4);
    if (idx >= tot4) return;
    int wq4 = (int)(idx % (W2 / 4)) * 4;
    int h2 = (int)((idx / (W2 / 4)) % H2);
    long bn = idx / ((long)(W2 / 4) * H2);

    float fh = h2 * 0.5f - 0.25f;
    int h0f = (int)floorf(fh);
    float wh = fh - (float)h0f;
    int h0 = max(h0f, 0), h1 = min(h0f + 1, Hh - 1);

    const float* r0 = m + bn * (long)HW + h0 * Ww;
    const float* r1 = m + bn * (long)HW + h1 * Ww;
    float o = off[bn];

    float r[4];
#pragma unroll
    for (int j = 0; j < 4; j++) {
        int w2 = wq4 + j;
        float fw = w2 * 0.5f - 0.25f;
        int w0f = (int)floorf(fw);
        float ww = fw - (float)w0f;
        int w0 = max(w0f, 0), w1 = min(w0f + 1, Ww - 1);
        float t0 = r0[w0] * (1.f - ww) + r0[w1] * ww;
        float t1 = r1[w0] * (1.f - ww) + r1[w1] * ww;
        r[j] = t0 * (1.f - wh) + t1 * wh + o;
    }
    float4 v = make_float4(r[0], r[1], r[2], r[3]);
    *(float4*)(out + bn * (long)(H2 * W2) + (long)h2 * W2 + wq4) = v;
}

// ---------------- launcher ----------------
extern "C" void kernel_launch(void* const* d_in, const int* in_sizes, int n_in,
                              void* d_out, int out_size)
{
    const float* spat    = (const float*)d_in[0];
    const float* qf      = (const float*)d_in[1];
    const float* dw_w    = (const float*)d_in[2];
    const float* dw_b    = (const float*)d_in[3];
    const float* ln_w    = (const float*)d_in[4];
    const float* ln_b    = (const float*)d_in[5];
    const float* pw_w    = (const float*)d_in[6];
    const float* pw_b    = (const float*)d_in[7];
    const float* sproj_w = (const float*)d_in[8];
    const float* sproj_b = (const float*)d_in[9];
    const float* mlp_w1  = (const float*)d_in[10];
    const float* mlp_b1  = (const float*)d_in[11];
    const float* mlp_w2  = (const float*)d_in[12];
    const float* mlp_b2  = (const float*)d_in[13];
    const float* mlp_w3  = (const float*)d_in[14];
    const float* mlp_b3  = (const float*)d_in[15];
    const float* qproj_w = (const float*)d_in[16];
    const float* qproj_b = (const float*)d_in[17];
    const float* head_b  = (const float*)d_in[18];
    float* out = (float*)d_out;

    float *px, *py, *pt, *pmean, *pinv, *pq1, *pq2, *pq4, *pqq, *poff, *pm;
    cudaGetSymbolAddress((void**)&px,    g_x);
    cudaGetSymbolAddress((void**)&py,    g_y);
    cudaGetSymbolAddress((void**)&pt,    g_t);
    cudaGetSymbolAddress((void**)&pmean, g_mean);
    cudaGetSymbolAddress((void**)&pinv,  g_inv);
    cudaGetSymbolAddress((void**)&pq1,   g_q1);
    cudaGetSymbolAddress((void**)&pq2,   g_q2);
    cudaGetSymbolAddress((void**)&pq4,   g_q4);
    cudaGetSymbolAddress((void**)&pqq,   g_qq);
    cudaGetSymbolAddress((void**)&poff,  g_off);
    cudaGetSymbolAddress((void**)&pm,    g_m);

    dim3 dwBlock(80, 4);
    dim3 dwGrid(1, Hh / 4, Bb * Cc);
    const int pix = Bb * HW;

    // ---- spatial block 0: dw -> stats -> pw GEMM (LN fused) + GELU + residual ----
    dw_kernel<<<dwGrid, dwBlock>>>(spat, dw_w, dw_b, pt);
    stats_kernel<<<(pix + 255) / 256, 256>>>(pt, pmean, pinv);
    gemm2<2, 0, 1, true, true><<<dim3(HW / 128, 2, Bb), 256>>>(
        pw_w, pt, pw_b, spat, pmean, pinv, ln_w, ln_b,
        px, Cc, HW, Cc, 0, CHW, CHW);

    // ---- spatial block 1 ----
    dw_kernel<<<dwGrid, dwBlock>>>(px, dw_w + Cc * 9, dw_b + Cc, pt);
    stats_kernel<<<(pix + 255) / 256, 256>>>(pt, pmean, pinv);
    gemm2<2, 0, 1, true, true><<<dim3(HW / 128, 2, Bb), 256>>>(
        pw_w + Cc * Cc, pt, pw_b + Cc, px, pmean, pinv, ln_w + Cc, ln_b + Cc,
        py, Cc, HW, Cc, 0, CHW, CHW);

    // ---- query MLP chain (M = B*N = 1200 rows) ----
    const int Mq = Bb * Nq;
    gemm2<1, 1, 2, false, false><<<dim3(HID / 128, (Mq + 127) / 128, 1), 256>>>(
        qf, mlp_w1, mlp_b1, nullptr, nullptr, nullptr, nullptr, nullptr,
        pq1, Mq, HID, Cc, 0, 0, 0);
    gemm2<1, 1, 2, false, false><<<dim3(HID / 128, (Mq + 127) / 128, 1), 256>>>(
        pq1, mlp_w2, mlp_b2, nullptr, nullptr, nullptr, nullptr, nullptr,
        pq2, Mq, HID, HID, 0, 0, 0);
    gemm2<0, 1, 2, false, false><<<dim3(Cc / 128, (Mq + 127) / 128, 1), 256>>>(
        pq2, mlp_w3, mlp_b3, nullptr, nullptr, nullptr, nullptr, nullptr,
        pq1, Mq, Cc, HID, 0, 0, 0);                 // q3 (reuse q1)
    gemm2<0, 1, 2, false, false><<<dim3(IDim / 128, (Mq + 127) / 128, 1), 256>>>(
        pq1, qproj_w, qproj_b, nullptr, nullptr, nullptr, nullptr, nullptr,
        pq4, Mq, IDim, Cc, 0, 0, 0);                // q4
    // fold sproj into query side: qq[n,c] = sum_id q4[n,id] * sproj_w[id,c]
    gemm2<0, 0, 0, false, false><<<dim3(Cc / 128, (Mq + 127) / 128, 1), 256>>>(
        pq4, sproj_w, nullptr, nullptr, nullptr, nullptr, nullptr, nullptr,
        pqq, Mq, Cc, IDim, 0, 0, 0);
    off_kernel<<<(Mq + 255) / 256, 256>>>(pq4, sproj_b, head_b, poff);

    // ---- mask GEMM at 80x80: m[b,n,p] = sum_c qq[b,n,c] * y[b,c,p] ----
    gemm2<0, 0, 0, false, false><<<dim3(HW / 128, (Nq + 127) / 128, Bb), 256>>>(
        pqq, py, nullptr, nullptr, nullptr, nullptr, nullptr, nullptr,
        pm, Nq, HW, Cc, (long)Nq * Cc, (long)CHW, (long)Nq * HW);

    // ---- bilinear 2x upsample + per-(b,n) offset ----
    const long tot4 = (long)Bb * Nq * H2 * (W2 / 4);
    upsample_kernel<<<(unsigned)((tot4 + 255) / 256), 256>>>(pm, poff, out);
}

// round 4
// speedup vs baseline: 2.2395x; 1.3859x over previous
#include <cuda_runtime.h>
#include <cuda_bf16.h>
#include <math.h>
#include <stdint.h>

// ---------------- problem constants ----------------
#define Bb 4
#define Cc 256
#define Hh 80
#define Ww 80
#define Nq 300
#define IDim 128
#define HID 512
#define H2 160
#define W2 160
#define HW (Hh*Ww)
#define CHW (Cc*HW)

// ---------------- device scratch ----------------
__device__ float g_x[Bb*CHW];      // block0 output
__device__ float g_y[Bb*CHW];      // block1 output (final spatial)
__device__ float g_t[Bb*CHW];      // dw temp (pre-LN)
__device__ float g_mean[Bb*HW];
__device__ float g_inv[Bb*HW];
__device__ float g_q1[Bb*Nq*HID];
__device__ float g_q2[Bb*Nq*HID];
__device__ float g_q4[Bb*Nq*IDim];
__device__ float g_qq[Bb*Nq*Cc];
__device__ float g_off[Bb*Nq];
__device__ float g_m[Bb*Nq*HW];    // mask at 80x80

__device__ __forceinline__ float gelu_f(float x) {
    return 0.5f * x * (1.0f + erff(x * 0.70710678118654752f));
}
__device__ __forceinline__ uint32_t su32(const void* p) {
    return (uint32_t)__cvta_generic_to_shared(p);
}
__device__ __forceinline__ void ldsm4(uint32_t* r, uint32_t addr) {
    asm volatile("ldmatrix.sync.aligned.m8n8.x4.shared.b16 {%0,%1,%2,%3}, [%4];"
        : "=r"(r[0]), "=r"(r[1]), "=r"(r[2]), "=r"(r[3]) : "r"(addr));
}
__device__ __forceinline__ void ldsm2(uint32_t* r, uint32_t addr) {
    asm volatile("ldmatrix.sync.aligned.m8n8.x2.shared.b16 {%0,%1}, [%2];"
        : "=r"(r[0]), "=r"(r[1]) : "r"(addr));
}
__device__ __forceinline__ void mma16816(float* d, const uint32_t* a, const uint32_t* b) {
    asm volatile("mma.sync.aligned.m16n8k16.row.col.f32.bf16.bf16.f32 "
        "{%0,%1,%2,%3}, {%4,%5,%6,%7}, {%8,%9}, {%0,%1,%2,%3};"
        : "+f"(d[0]), "+f"(d[1]), "+f"(d[2]), "+f"(d[3])
        : "r"(a[0]), "r"(a[1]), "r"(a[2]), "r"(a[3]), "r"(b[0]), "r"(b[1]));
}
__device__ __forceinline__ void split_bf16(float x, __nv_bfloat16& hi, __nv_bfloat16& lo) {
    hi = __float2bfloat16(x);
    lo = __float2bfloat16(x - __bfloat162float(hi));
}

// ---------------- depthwise 3x3 conv (SAME) + bias ----------------
__global__ void dw_kernel(const float* __restrict__ x, const float* __restrict__ w,
                          const float* __restrict__ bia, float* __restrict__ out)
{
    int wq = threadIdx.x;
    int hq = blockIdx.y * 4 + threadIdx.y;
    int plane = blockIdx.z;
    int c = plane & (Cc - 1);
    const float* xp = x + (long)plane * HW;
    const float* wp = w + c * 9;
    float w00 = wp[0], w01 = wp[1], w02 = wp[2];
    float w10 = wp[3], w11 = wp[4], w12 = wp[5];
    float w20 = wp[6], w21 = wp[7], w22 = wp[8];
    float acc = bia[c];

    const float* r0 = xp + (hq - 1) * Ww;
    const float* r1 = xp + hq * Ww;
    const float* r2 = xp + (hq + 1) * Ww;
    bool ht = hq > 0, hb = hq < Hh - 1;
    bool wl = wq > 0, wr = wq < Ww - 1;

    if (ht) {
        if (wl) acc += w00 * r0[wq - 1];
        acc += w01 * r0[wq];
        if (wr) acc += w02 * r0[wq + 1];
    }
    {
        if (wl) acc += w10 * r1[wq - 1];
        acc += w11 * r1[wq];
        if (wr) acc += w12 * r1[wq + 1];
    }
    if (hb) {
        if (wl) acc += w20 * r2[wq - 1];
        acc += w21 * r2[wq];
        if (wr) acc += w22 * r2[wq + 1];
    }
    out[(long)plane * HW + hq * Ww + wq] = acc;
}

// ---------------- LN stats per pixel (mean, inv-std) ----------------
__global__ void stats_kernel(const float* __restrict__ t,
                             float* __restrict__ mean, float* __restrict__ inv)
{
    int p = blockIdx.x * blockDim.x + threadIdx.x;
    if (p >= Bb*HW) return;
    int bb = p / HW;
    int pix = p - bb * HW;
    const float* base = t + (long)bb * CHW + pix;
    float s = 0.f, s2 = 0.f;
#pragma unroll 8
    for (int c = 0; c < Cc; c++) {
        float v = base[(long)c * HW];
        s += v; s2 += v * v;
    }
    float m = s * (1.0f / Cc);
    float var = s2 * (1.0f / Cc) - m * m;
    mean[p] = m;
    inv[p] = rsqrtf(var + 1e-6f);
}

// ---------------- tensor-core GEMM (bf16 3-pass split) ----------------
// C[m,n] = act( sum_k A[m,k] * Bop[k,n] + bias ) (+ resid)
// BMODE 0: Bop = B[k,n] (row stride N), optional per-element LN fusion.
// BMODE 1: Bop = B[n,k] (row stride K).
// Tiles: BM=128, BN=64, BK=16. 8 warps (4m x 2n), warp tile 32x32.
// mma.sync m16n8k16 bf16, split hi/lo, 3 passes: Ah*Bh + Ah*Bl + Al*Bh.
// PADK=24 bf16 (48B row stride, multiple of 16B for ldmatrix; 12-bank stride
// -> 8 ldmatrix rows hit 8 distinct banks).
#define PADK 24

template<int ACT, int BMODE, int BIASM, bool LNF, bool RES>
__global__ void __launch_bounds__(256)
gemm_tc(const float* __restrict__ A, const float* __restrict__ B,
        const float* __restrict__ bias, const float* __restrict__ resid,
        const float* __restrict__ lnMean, const float* __restrict__ lnInv,
        const float* __restrict__ lnW, const float* __restrict__ lnB,
        float* __restrict__ C, int M, int N, int K,
        long sA, long sB, long sC)
{
    int z = blockIdx.z;
    A += z * sA; B += z * sB; C += z * sC;
    const float* R = RES ? (resid + z * sC) : nullptr;

    int m0 = blockIdx.y * 128;
    int n0 = blockIdx.x * 64;

    __shared__ __align__(16) __nv_bfloat16 As[2][2][128 * PADK];
    __shared__ __align__(16) __nv_bfloat16 Bs[2][2][64 * PADK];

    int tid = threadIdx.x;
    int warp = tid >> 5;
    int lane = tid & 31;
    int wm = warp & 3;        // 0..3 -> m offset 32*wm
    int wn = warp >> 2;       // 0..1 -> n offset 32*wn

    // ---- loader indices ----
    int arow = tid >> 1;                  // 0..127
    int acol = (tid & 1) * 8;             // 0 or 8
    // BMODE1
    int b1row = tid >> 2;                 // 0..63 (n)
    int b1col = (tid & 3) * 4;            // 0..12 (k)
    // BMODE0
    int b0k = tid >> 4;                   // 0..15 (k)
    int b0n = (tid & 15) * 4;             // 0..60 (n)

    float4 mvec = make_float4(0.f,0.f,0.f,0.f), ivec = mvec;
    if (LNF) {
        mvec = *(const float4*)(lnMean + (long)z * N + n0 + b0n);
        ivec = *(const float4*)(lnInv  + (long)z * N + n0 + b0n);
    }

    float acc[2][4][4];
#pragma unroll
    for (int i = 0; i < 2; i++)
#pragma unroll
        for (int j = 0; j < 4; j++)
#pragma unroll
            for (int q = 0; q < 4; q++) acc[i][j][q] = 0.f;

    const int KT = K >> 4;
    int gm_ld = m0 + arow;
    bool mok = gm_ld < M;
    const float* Aip = A + (long)gm_ld * K + acol;

    float4 pa0, pa1, pb;
    // ---- load chunk 0 ----
    {
        pa0 = mok ? *(const float4*)(Aip + 0) : make_float4(0,0,0,0);
        pa1 = mok ? *(const float4*)(Aip + 4) : make_float4(0,0,0,0);
        if (BMODE == 1) {
            pb = *(const float4*)(B + (long)(n0 + b1row) * K + b1col);
        } else {
            pb = *(const float4*)(B + (long)b0k * N + n0 + b0n);
            if (LNF) {
                float lwk = lnW[b0k], lbk = lnB[b0k];
                pb.x = (pb.x - mvec.x) * ivec.x * lwk + lbk;
                pb.y = (pb.y - mvec.y) * ivec.y * lwk + lbk;
                pb.z = (pb.z - mvec.z) * ivec.z * lwk + lbk;
                pb.w = (pb.w - mvec.w) * ivec.w * lwk + lbk;
            }
        }
    }
    // ---- store chunk 0 into buf 0 ----
    {
        float v[8] = {pa0.x, pa0.y, pa0.z, pa0.w, pa1.x, pa1.y, pa1.z, pa1.w};
        __nv_bfloat162* p0 = (__nv_bfloat162*)&As[0][0][arow * PADK + acol];
        __nv_bfloat162* p1 = (__nv_bfloat162*)&As[0][1][arow * PADK + acol];
#pragma unroll
        for (int j = 0; j < 4; j++) {
            __nv_bfloat16 h0, l0, h1, l1;
            split_bf16(v[2*j], h0, l0);
            split_bf16(v[2*j+1], h1, l1);
            p0[j] = __nv_bfloat162(h0, h1);
            p1[j] = __nv_bfloat162(l0, l1);
        }
        float bv[4] = {pb.x, pb.y, pb.z, pb.w};
        if (BMODE == 1) {
            __nv_bfloat162* q0 = (__nv_bfloat162*)&Bs[0][0][b1row * PADK + b1col];
            __nv_bfloat162* q1 = (__nv_bfloat162*)&Bs[0][1][b1row * PADK + b1col];
#pragma unroll
            for (int j = 0; j < 2; j++) {
                __nv_bfloat16 h0, l0, h1, l1;
                split_bf16(bv[2*j], h0, l0);
                split_bf16(bv[2*j+1], h1, l1);
                q0[j] = __nv_bfloat162(h0, h1);
                q1[j] = __nv_bfloat162(l0, l1);
            }
        } else {
#pragma unroll
            for (int j = 0; j < 4; j++) {
                __nv_bfloat16 h, l;
                split_bf16(bv[j], h, l);
                Bs[0][0][(b0n + j) * PADK + b0k] = h;
                Bs[0][1][(b0n + j) * PADK + b0k] = l;
            }
        }
    }
    __syncthreads();

    // ldmatrix address indices (fixed per thread)
    int a_mrow = lane & 15;
    int a_kcol = (lane >> 4) * 8;
    int b_nrow = lane & 7;
    int b_kcol = ((lane >> 3) & 1) * 8;

    for (int kt = 0; kt < KT; kt++) {
        int buf = kt & 1;
        // ---- prefetch chunk kt+1 ----
        if (kt + 1 < KT) {
            int kb = (kt + 1) << 4;
            pa0 = mok ? *(const float4*)(Aip + kb + 0) : make_float4(0,0,0,0);
            pa1 = mok ? *(const float4*)(Aip + kb + 4) : make_float4(0,0,0,0);
            if (BMODE == 1) {
                pb = *(const float4*)(B + (long)(n0 + b1row) * K + kb + b1col);
            } else {
                pb = *(const float4*)(B + (long)(kb + b0k) * N + n0 + b0n);
                if (LNF) {
                    float lwk = lnW[kb + b0k], lbk = lnB[kb + b0k];
                    pb.x = (pb.x - mvec.x) * ivec.x * lwk + lbk;
                    pb.y = (pb.y - mvec.y) * ivec.y * lwk + lbk;
                    pb.z = (pb.z - mvec.z) * ivec.z * lwk + lbk;
                    pb.w = (pb.w - mvec.w) * ivec.w * lwk + lbk;
                }
            }
        }

        // ---- compute on buf ----
        uint32_t afr[2][2][4];   // [split][mt][4]
        uint32_t bfr[2][4][2];   // [split][nt][2]
#pragma unroll
        for (int s = 0; s < 2; s++) {
#pragma unroll
            for (int mt = 0; mt < 2; mt++) {
                uint32_t addr = su32(&As[buf][s][(wm*32 + mt*16 + a_mrow) * PADK + a_kcol]);
                ldsm4(afr[s][mt], addr);
            }
#pragma unroll
            for (int nt = 0; nt < 4; nt++) {
                uint32_t addr = su32(&Bs[buf][s][(wn*32 + nt*8 + b_nrow) * PADK + b_kcol]);
                ldsm2(bfr[s][nt], addr);
            }
        }
#pragma unroll
        for (int mt = 0; mt < 2; mt++)
#pragma unroll
            for (int nt = 0; nt < 4; nt++) {
                mma16816(acc[mt][nt], afr[0][mt], bfr[0][nt]);  // hi*hi
                mma16816(acc[mt][nt], afr[0][mt], bfr[1][nt]);  // hi*lo
                mma16816(acc[mt][nt], afr[1][mt], bfr[0][nt]);  // lo*hi
            }

        // ---- store prefetched chunk into other buffer ----
        if (kt + 1 < KT) {
            int nb = buf ^ 1;
            float v[8] = {pa0.x, pa0.y, pa0.z, pa0.w, pa1.x, pa1.y, pa1.z, pa1.w};
            __nv_bfloat162* p0 = (__nv_bfloat162*)&As[nb][0][arow * PADK + acol];
            __nv_bfloat162* p1 = (__nv_bfloat162*)&As[nb][1][arow * PADK + acol];
#pragma unroll
            for (int j = 0; j < 4; j++) {
                __nv_bfloat16 h0, l0, h1, l1;
                split_bf16(v[2*j], h0, l0);
                split_bf16(v[2*j+1], h1, l1);
                p0[j] = __nv_bfloat162(h0, h1);
                p1[j] = __nv_bfloat162(l0, l1);
            }
            float bv[4] = {pb.x, pb.y, pb.z, pb.w};
            if (BMODE == 1) {
                __nv_bfloat162* q0 = (__nv_bfloat162*)&Bs[nb][0][b1row * PADK + b1col];
                __nv_bfloat162* q1 = (__nv_bfloat162*)&Bs[nb][1][b1row * PADK + b1col];
#pragma unroll
                for (int j = 0; j < 2; j++) {
                    __nv_bfloat16 h0, l0, h1, l1;
                    split_bf16(bv[2*j], h0, l0);
                    split_bf16(bv[2*j+1], h1, l1);
                    q0[j] = __nv_bfloat162(h0, h1);
                    q1[j] = __nv_bfloat162(l0, l1);
                }
            } else {
#pragma unroll
                for (int j = 0; j < 4; j++) {
                    __nv_bfloat16 h, l;
                    split_bf16(bv[j], h, l);
                    Bs[nb][0][(b0n + j) * PADK + b0k] = h;
                    Bs[nb][1][(b0n + j) * PADK + b0k] = l;
                }
            }
            __syncthreads();
        }
    }

    // ---- epilogue ----
#pragma unroll
    for (int mt = 0; mt < 2; mt++) {
#pragma unroll
        for (int nt = 0; nt < 4; nt++) {
            int gn = n0 + wn*32 + nt*8 + (lane & 3) * 2;
            float bn0v = 0.f, bn1v = 0.f;
            if (BIASM == 2) { bn0v = bias[gn]; bn1v = bias[gn + 1]; }
#pragma unroll
            for (int h = 0; h < 2; h++) {
                int row = m0 + wm*32 + mt*16 + (lane >> 2) + h*8;
                if (row >= M) continue;
                float x0 = acc[mt][nt][h*2 + 0];
                float x1 = acc[mt][nt][h*2 + 1];
                if (BIASM == 1) { float bm = bias[row]; x0 += bm; x1 += bm; }
                if (BIASM == 2) { x0 += bn0v; x1 += bn1v; }
                if (ACT == 1) { x0 = fmaxf(x0, 0.f); x1 = fmaxf(x1, 0.f); }
                if (ACT == 2) { x0 = gelu_f(x0); x1 = gelu_f(x1); }
                if (RES) {
                    float2 r2 = *(const float2*)&R[(long)row * N + gn];
                    x0 += r2.x; x1 += r2.y;
                }
                float2 o; o.x = x0; o.y = x1;
                *(float2*)&C[(long)row * N + gn] = o;
            }
        }
    }
}

// ---------------- per-query offset: q4 . sproj_b + head_bias ----------------
__global__ void off_kernel(const float* __restrict__ q4, const float* __restrict__ sb,
                           const float* __restrict__ hb, float* __restrict__ off)
{
    int n = blockIdx.x * blockDim.x + threadIdx.x;
    if (n >= Bb*Nq) return;
    float s = hb[0];
#pragma unroll 8
    for (int i = 0; i < IDim; i++) s += q4[(long)n * IDim + i] * sb[i];
    off[n] = s;
}

// ---------------- bilinear 2x upsample + offset, float4 stores ----------------
__global__ void upsample_kernel(const float* __restrict__ m, const float* __restrict__ off,
                                float* __restrict__ out)
{
    long idx = (long)blockIdx.x * blockDim.x + threadIdx.x;
    const long tot4 = (long)Bb * Nq * H2 * (W2 / 4);
    if (idx >= tot4) return;
    int wq4 = (int)(idx % (W2 / 4)) * 4;
    int h2 = (int)((idx / (W2 / 4)) % H2);
    long bn = idx / ((long)(W2 / 4) * H2);

    float fh = h2 * 0.5f - 0.25f;
    int h0f = (int)floorf(fh);
    float wh = fh - (float)h0f;
    int h0 = max(h0f, 0), h1 = min(h0f + 1, Hh - 1);

    const float* r0 = m + bn * (long)HW + h0 * Ww;
    const float* r1 = m + bn * (long)HW + h1 * Ww;
    float o = off[bn];

    float r[4];
#pragma unroll
    for (int j = 0; j < 4; j++) {
        int w2 = wq4 + j;
        float fw = w2 * 0.5f - 0.25f;
        int w0f = (int)floorf(fw);
        float ww = fw - (float)w0f;
        int w0 = max(w0f, 0), w1 = min(w0f + 1, Ww - 1);
        float t0 = r0[w0] * (1.f - ww) + r0[w1] * ww;
        float t1 = r1[w0] * (1.f - ww) + r1[w1] * ww;
        r[j] = t0 * (1.f - wh) + t1 * wh + o;
    }
    float4 v = make_float4(r[0], r[1], r[2], r[3]);
    *(float4*)(out + bn * (long)(H2 * W2) + (long)h2 * W2 + wq4) = v;
}

// ---------------- launcher ----------------
extern "C" void kernel_launch(void* const* d_in, const int* in_sizes, int n_in,
                              void* d_out, int out_size)
{
    const float* spat    = (const float*)d_in[0];
    const float* qf      = (const float*)d_in[1];
    const float* dw_w    = (const float*)d_in[2];
    const float* dw_b    = (const float*)d_in[3];
    const float* ln_w    = (const float*)d_in[4];
    const float* ln_b    = (const float*)d_in[5];
    const float* pw_w    = (const float*)d_in[6];
    const float* pw_b    = (const float*)d_in[7];
    const float* sproj_w = (const float*)d_in[8];
    const float* sproj_b = (const float*)d_in[9];
    const float* mlp_w1  = (const float*)d_in[10];
    const float* mlp_b1  = (const float*)d_in[11];
    const float* mlp_w2  = (const float*)d_in[12];
    const float* mlp_b2  = (const float*)d_in[13];
    const float* mlp_w3  = (const float*)d_in[14];
    const float* mlp_b3  = (const float*)d_in[15];
    const float* qproj_w = (const float*)d_in[16];
    const float* qproj_b = (const float*)d_in[17];
    const float* head_b  = (const float*)d_in[18];
    float* out = (float*)d_out;

    float *px, *py, *pt, *pmean, *pinv, *pq1, *pq2, *pq4, *pqq, *poff, *pm;
    cudaGetSymbolAddress((void**)&px,    g_x);
    cudaGetSymbolAddress((void**)&py,    g_y);
    cudaGetSymbolAddress((void**)&pt,    g_t);
    cudaGetSymbolAddress((void**)&pmean, g_mean);
    cudaGetSymbolAddress((void**)&pinv,  g_inv);
    cudaGetSymbolAddress((void**)&pq1,   g_q1);
    cudaGetSymbolAddress((void**)&pq2,   g_q2);
    cudaGetSymbolAddress((void**)&pq4,   g_q4);
    cudaGetSymbolAddress((void**)&pqq,   g_qq);
    cudaGetSymbolAddress((void**)&poff,  g_off);
    cudaGetSymbolAddress((void**)&pm,    g_m);

    dim3 dwBlock(80, 4);
    dim3 dwGrid(1, Hh / 4, Bb * Cc);
    const int pix = Bb * HW;
    const int Mq = Bb * Nq;

    // ---- spatial block 0: dw -> stats -> pw GEMM (LN fused) + GELU + residual ----
    dw_kernel<<<dwGrid, dwBlock>>>(spat, dw_w, dw_b, pt);
    stats_kernel<<<(pix + 255) / 256, 256>>>(pt, pmean, pinv);
    gemm_tc<2, 0, 1, true, true><<<dim3(HW / 64, 2, Bb), 256>>>(
        pw_w, pt, pw_b, spat, pmean, pinv, ln_w, ln_b,
        px, Cc, HW, Cc, 0, CHW, CHW);

    // ---- spatial block 1 ----
    dw_kernel<<<dwGrid, dwBlock>>>(px, dw_w + Cc * 9, dw_b + Cc, pt);
    stats_kernel<<<(pix + 255) / 256, 256>>>(pt, pmean, pinv);
    gemm_tc<2, 0, 1, true, true><<<dim3(HW / 64, 2, Bb), 256>>>(
        pw_w + Cc * Cc, pt, pw_b + Cc, px, pmean, pinv, ln_w + Cc, ln_b + Cc,
        py, Cc, HW, Cc, 0, CHW, CHW);

    // ---- query MLP chain (M = 1200) ----
    gemm_tc<1, 1, 2, false, false><<<dim3(HID / 64, (Mq + 127) / 128, 1), 256>>>(
        qf, mlp_w1, mlp_b1, nullptr, nullptr, nullptr, nullptr, nullptr,
        pq1, Mq, HID, Cc, 0, 0, 0);
    gemm_tc<1, 1, 2, false, false><<<dim3(HID / 64, (Mq + 127) / 128, 1), 256>>>(
        pq1, mlp_w2, mlp_b2, nullptr, nullptr, nullptr, nullptr, nullptr,
        pq2, Mq, HID, HID, 0, 0, 0);
    gemm_tc<0, 1, 2, false, false><<<dim3(Cc / 64, (Mq + 127) / 128, 1), 256>>>(
        pq2, mlp_w3, mlp_b3, nullptr, nullptr, nullptr, nullptr, nullptr,
        pq1, Mq, Cc, HID, 0, 0, 0);                 // q3 (reuse q1)
    gemm_tc<0, 1, 2, false, false><<<dim3(IDim / 64, (Mq + 127) / 128, 1), 256>>>(
        pq1, qproj_w, qproj_b, nullptr, nullptr, nullptr, nullptr, nullptr,
        pq4, Mq, IDim, Cc, 0, 0, 0);                // q4
    // fold sproj into query side: qq[n,c] = sum_id q4[n,id] * sproj_w[id,c]
    gemm_tc<0, 0, 0, false, false><<<dim3(Cc / 64, (Mq + 127) / 128, 1), 256>>>(
        pq4, sproj_w, nullptr, nullptr, nullptr, nullptr, nullptr, nullptr,
        pqq, Mq, Cc, IDim, 0, 0, 0);
    off_kernel<<<(Mq + 255) / 256, 256>>>(pq4, sproj_b, head_b, poff);

    // ---- mask GEMM at 80x80: m[b,n,p] = sum_c qq[b,n,c] * y[b,c,p] ----
    gemm_tc<0, 0, 0, false, false><<<dim3(HW / 64, (Nq + 127) / 128, Bb), 256>>>(
        pqq, py, nullptr, nullptr, nullptr, nullptr, nullptr, nullptr,
        pm, Nq, HW, Cc, (long)Nq * Cc, (long)CHW, (long)Nq * HW);

    // ---- bilinear 2x upsample + per-(b,n) offset ----
    const long tot4 = (long)Bb * Nq * H2 * (W2 / 4);
    upsample_kernel<<<(unsigned)((tot4 + 255) / 256), 256>>>(pm, poff, out);
}